// round 15
// baseline (speedup 1.0000x reference)
#include <cuda_runtime.h>
#include <cstdint>

typedef unsigned long long u64;
#define DEV static __device__ __forceinline__

static constexpr int L_ = 3;
static constexpr int NB = 128;   // 128 CTAs, 8 rows each
static constexpr int NT = 512;   // 16 warps

// ---------------- device globals ----------------
__device__ float g_P[2][1024 * 128];   // double-buffered Pj
__device__ float g_Wc[L_][128 * 128];  // ew2 @ nw1b
__device__ float g_cb[L_][128];        // eb2 @ nw1b
__device__ unsigned g_bar[4];          // monotonic barrier counters (replay-safe)

// ---------------- f32x2 helpers ----------------
DEV u64 pk(float lo, float hi) {
    u64 r; asm("mov.b64 %0,{%1,%2};" : "=l"(r) : "f"(lo), "f"(hi)); return r;
}
DEV void upk(u64 v, float& lo, float& hi) {
    asm("mov.b64 {%0,%1},%2;" : "=f"(lo), "=f"(hi) : "l"(v));
}
DEV u64 add2(u64 a, u64 b) {
    u64 r; asm("add.rn.f32x2 %0,%1,%2;" : "=l"(r) : "l"(a), "l"(b)); return r;
}
DEV u64 fma2(u64 a, u64 b, u64 c) {
    u64 r; asm("fma.rn.f32x2 %0,%1,%2,%3;" : "=l"(r) : "l"(a), "l"(b), "l"(c)); return r;
}
DEV u64 relu2(u64 v) {
    float lo, hi; upk(v, lo, hi);
    return pk(fmaxf(lo, 0.f), fmaxf(hi, 0.f));
}

// ---------------- split grid barrier (monotonic counters; replay-safe) ----------------
DEV unsigned ld_acq(const unsigned* p) {
    unsigned v;
    asm volatile("ld.acquire.gpu.global.u32 %0,[%1];" : "=r"(v) : "l"(p) : "memory");
    return v;
}
DEV void bar_arrive(int bidx, int tid, unsigned* sT) {
    __syncthreads();
    if (tid == 0) {
        __threadfence();
        unsigned t = atomicAdd(&g_bar[bidx], 1u);
        *sT = (t / (unsigned)NB + 1u) * (unsigned)NB;
    }
}
DEV void bar_wait(int bidx, int tid, unsigned* sT) {
    __syncthreads();
    if (tid == 0) {
        unsigned target = *sT;
        while (ld_acq(&g_bar[bidx]) < target) { __nanosleep(64); }
        __threadfence();
    }
    __syncthreads();
}

// ---------------- r=4 k-split-8 GEMM, W direct from global via __ldg --------------
// warp = (rg = w&1, kq = w>>1 of 8, 16 k each), lane = 4 cols.
// dup'd A layout: ATs[k*20 + 2r] = ATs[k*20+2r+1] = A[r][k]
DEV void gemm_g(const float* __restrict__ ATs, const float* __restrict__ W,
                int lane, int rg, int kq, u64 acc[4][2]) {
    const float* ap = ATs + kq * 16 * 20 + rg * 8;
    const float* wp = W + kq * 16 * 128 + lane * 4;
#pragma unroll
    for (int k = 0; k < 16; k++) {
        ulonglong2 wv = __ldg((const ulonglong2*)(wp + k * 128));
        ulonglong2 a01 = *(const ulonglong2*)(ap + k * 20);
        ulonglong2 a23 = *(const ulonglong2*)(ap + k * 20 + 4);
        acc[0][0] = fma2(a01.x, wv.x, acc[0][0]);
        acc[0][1] = fma2(a01.x, wv.y, acc[0][1]);
        acc[1][0] = fma2(a01.y, wv.x, acc[1][0]);
        acc[1][1] = fma2(a01.y, wv.y, acc[1][1]);
        acc[2][0] = fma2(a23.x, wv.x, acc[2][0]);
        acc[2][1] = fma2(a23.x, wv.y, acc[2][1]);
        acc[3][0] = fma2(a23.y, wv.x, acc[3][0]);
        acc[3][1] = fma2(a23.y, wv.y, acc[3][1]);
    }
}

// ---------------- merged 8x256 GEMM: warp=(cg2,rg2,kq4), 32 k each, W via __ldg ----
DEV void gemm_m_g(const float* __restrict__ ATs, const float* __restrict__ W,
                  int lane, int rg, int kq, u64 acc[4][2]) {
    const float* ap = ATs + kq * 32 * 20 + rg * 8;
    const float* wp = W + kq * 32 * 128 + lane * 4;
#pragma unroll 16
    for (int k = 0; k < 32; k++) {
        ulonglong2 wv = __ldg((const ulonglong2*)(wp + k * 128));
        ulonglong2 a01 = *(const ulonglong2*)(ap + k * 20);
        ulonglong2 a23 = *(const ulonglong2*)(ap + k * 20 + 4);
        acc[0][0] = fma2(a01.x, wv.x, acc[0][0]);
        acc[0][1] = fma2(a01.x, wv.y, acc[0][1]);
        acc[1][0] = fma2(a01.y, wv.x, acc[1][0]);
        acc[1][1] = fma2(a01.y, wv.y, acc[1][1]);
        acc[2][0] = fma2(a23.x, wv.x, acc[2][0]);
        acc[2][1] = fma2(a23.x, wv.y, acc[2][1]);
        acc[3][0] = fma2(a23.y, wv.x, acc[3][0]);
        acc[3][1] = fma2(a23.y, wv.y, acc[3][1]);
    }
}

DEV void store_part8(float* sPart, const u64 acc[4][2], int lane, int rg, int kq) {
    float* o = sPart + kq * 1024 + rg * 4 * 128 + lane * 4;
#pragma unroll
    for (int r = 0; r < 4; r++) {
        float v0, v1, v2, v3;
        upk(acc[r][0], v0, v1); upk(acc[r][1], v2, v3);
        *(float4*)(o + r * 128) = make_float4(v0, v1, v2, v3);
    }
}

// u64 pair-reduce: f0 = even float offset of the pair; partial stride 1024
DEV u64 reduce8_2(const float* __restrict__ sPart, int f0) {
    u64 p0 = *(const u64*)(sPart + f0);
    u64 p1 = *(const u64*)(sPart + f0 + 1024);
    u64 p2 = *(const u64*)(sPart + f0 + 2048);
    u64 p3 = *(const u64*)(sPart + f0 + 3072);
    u64 p4 = *(const u64*)(sPart + f0 + 4096);
    u64 p5 = *(const u64*)(sPart + f0 + 5120);
    u64 p6 = *(const u64*)(sPart + f0 + 6144);
    u64 p7 = *(const u64*)(sPart + f0 + 7168);
    return add2(add2(add2(p0, p1), add2(p2, p3)), add2(add2(p4, p5), add2(p6, p7)));
}

// u64 pair-reduce over 4 partials with stride 2048 (merged GEMM)
DEV u64 reduce4_2(const float* __restrict__ sPart, int f0) {
    u64 p0 = *(const u64*)(sPart + f0);
    u64 p1 = *(const u64*)(sPart + f0 + 2048);
    u64 p2 = *(const u64*)(sPart + f0 + 4096);
    u64 p3 = *(const u64*)(sPart + f0 + 6144);
    return add2(add2(p0, p1), add2(p2, p3));
}

// ---------------- smem layout (floats) ----------------
// sPart 0 (8192) | sATs 8192 (2560) | sNTs 10752 (2560) | sPi 13312 (1024)
// sPn 14336 (1024) | sAdj2 15360 (4096) | s_rs 19456 (8) | sX 19464 (1024)
// sBarT 20488 (1)
static constexpr int SMEM_FLOATS = 20489;   // 81956 B

__global__ void __launch_bounds__(NT, 1) k_main(
    float* __restrict__ x, const float* __restrict__ nf, const float* __restrict__ adj,
    const float* __restrict__ ew1, const float* __restrict__ eb1,
    const float* __restrict__ ew2, const float* __restrict__ eb2,
    const float* __restrict__ nw1, const float* __restrict__ nb1,
    const float* __restrict__ nw2, const float* __restrict__ nb2) {
    extern __shared__ float sm[];
    float* sPart = sm;
    float* sATs = sm + 8192;
    float* sNTs = sm + 10752;
    float* sPi = sm + 13312;
    float* sPn = sm + 14336;
    float* sAdj2 = sm + 15360;
    float* s_rs = sm + 19456;
    float* sX = sm + 19464;
    unsigned* sBarT = (unsigned*)(sm + 20488);

    int tid = threadIdx.x, lane = tid & 31, w = tid >> 5;
    int rb = blockIdx.x;        // rows rb*8 .. rb*8+7
    int b = rb >> 5;            // batch
    int il0 = (rb & 31) * 8;    // local i base in batch
    int rg = w & 1, kq = w >> 1;              // r4k8 roles
    int mcg = w & 1, mrg = (w >> 1) & 1, mkq = w >> 2;   // merged-GEMM roles
    int pr = tid >> 6;                        // pair-epilogue row
    int pc = (2 * tid) & 127;                 // pair-epilogue col0
    int pf0 = 2 * tid;                        // pair-epilogue float offset

    // ================= setup: produce Wc/cb, arrive, local setup, wait ==========
    if (rb < 48) {   // Wc[l] = ew2[l] @ nw1b[l]
        int l = rb / 16, r8 = rb % 16;
#pragma unroll
        for (int q = 0; q < 2; q++) {
            int idx = q * 512 + tid;
            int r = idx >> 7, k = idx & 127;
            float v = ew2[l * 16384 + (r8 * 8 + r) * 128 + k];
            *(float2*)(sATs + k * 20 + 2 * r) = make_float2(v, v);
        }
        __syncthreads();
        u64 acc[4][2] = {};
        gemm_g(sATs, nw1 + l * 32768 + 16384, lane, rg, kq, acc);
        store_part8(sPart, acc, lane, rg, kq);
        __syncthreads();
        *(u64*)(g_Wc[l] + (r8 * 8 + pr) * 128 + pc) = reduce8_2(sPart, pf0);
    } else if (rb == 48) {
        if (tid < 384) {
            int l = tid >> 7, c = tid & 127;
            const float* e2 = eb2 + l * 128;
            const float* W = nw1 + l * 32768 + 16384 + c;
            float s = 0.f;
#pragma unroll 8
            for (int m = 0; m < 128; m++) s = fmaf(e2[m], W[m * 128], s);
            g_cb[l][c] = s;
        }
    }
    bar_arrive(0, tid, sBarT);

    // ---- CTA-local setup, overlapped with other CTAs' Wc work ----
#pragma unroll
    for (int q = 0; q < 2; q++) sX[q * 512 + tid] = nf[rb * 1024 + q * 512 + tid];
    const float* adjb = adj + (size_t)(b * 256 + il0) * 256;
#pragma unroll
    for (int e = 0; e < 4; e++) {
        int idx = e * 512 + tid;
        int r = idx >> 8, j = idx & 255;
        float v = adjb[r * 256 + j];
        *(float2*)(sAdj2 + j * 16 + 2 * r) = make_float2(v, v);
    }
    if (w < 8) {
        float s = 0.f;
        const float* row = adjb + w * 256;
#pragma unroll
        for (int j = lane; j < 256; j += 32) s += row[j];
#pragma unroll
        for (int o = 16; o; o >>= 1) s += __shfl_xor_sync(~0u, s, o);
        if (!lane) s_rs[w] = s;
    }
    // pre-loop: dup'd sATs from sX (own values)
#pragma unroll
    for (int q = 0; q < 2; q++) {
        int idx = q * 512 + tid;
        int r = idx >> 7, k = idx & 127;
        float v = sX[idx];
        *(float2*)(sATs + k * 20 + 2 * r) = make_float2(v, v);
    }
    bar_wait(0, tid, sBarT);   // also orders sATs init before layer-0 GEMM reads

    // ================= layers =================
    for (int l = 0; l < L_; l++) {
        float* Pbuf = g_P[l & 1];
        const float* ew1l = ew1 + l * 32768;

        // ---- Pj = x @ ew1b -> global (stcg), then ARRIVE ----
        {
            u64 acc[4][2] = {};
            gemm_g(sATs, ew1l + 16384, lane, rg, kq, acc);
            store_part8(sPart, acc, lane, rg, kq);
            __syncthreads();
            __stcg((u64*)(Pbuf + (rb * 8 + pr) * 128 + pc), reduce8_2(sPart, pf0));
        }
        bar_arrive(1 + l, tid, sBarT);             // Pj published (sync inside)

        // ---- merged: [Pi|Pn] = x @ [ew1a | nw1a] + [eb1|nb1] (hidden behind barrier) ----
        {
            u64 acc[4][2] = {};
            gemm_m_g(sATs, mcg ? (nw1 + l * 32768) : ew1l, lane, mrg, mkq, acc);
            {   // store to sPart[kq][8r][256c]
                float* o = sPart + mkq * 2048 + mrg * 4 * 256 + mcg * 128 + lane * 4;
#pragma unroll
                for (int r = 0; r < 4; r++) {
                    float v0, v1, v2, v3;
                    upk(acc[r][0], v0, v1); upk(acc[r][1], v2, v3);
                    *(float4*)(o + r * 256) = make_float4(v0, v1, v2, v3);
                }
            }
            __syncthreads();
#pragma unroll
            for (int q = 0; q < 2; q++) {
                int i = q * 512 + tid;             // pair index 0..1023
                int f0 = 2 * i;
                int r = f0 >> 8, c = f0 & 255;
                u64 v = reduce4_2(sPart, f0);
                if (c < 128) {
                    u64 bb = *(const u64*)(eb1 + l * 128 + c);
                    *(u64*)(sPi + r * 128 + c) = add2(v, bb);
                } else {
                    int c2 = c - 128;
                    u64 bb = *(const u64*)(nb1 + l * 128 + c2);
                    *(u64*)(sPn + r * 128 + c2) = add2(v, bb);
                }
            }
        }
        bar_wait(1 + l, tid, sBarT);   // all Pj visible; sPi/sPn complete

        // ---- agg: warp=(dh2, jq8), thread = 8 i x 2 d over 32 j (1x slab LDG) ----
        {
            int d0 = (w & 1) * 64 + lane * 2;
            int jq8 = w >> 1;
            u64 xi[8], aacc[8];
#pragma unroll
            for (int i = 0; i < 8; i++) {
                xi[i] = *(const u64*)(sPi + i * 128 + d0);
                aacc[i] = 0ull;
            }
            const float* pj = Pbuf + b * 32768 + jq8 * 32 * 128 + d0;
            const float* ad = sAdj2 + jq8 * 32 * 16;
#pragma unroll 8
            for (int jj = 0; jj < 32; jj++) {
                u64 xj = __ldcg((const u64*)(pj + jj * 128));
                ulonglong2 a01 = *(const ulonglong2*)(ad + jj * 16);
                ulonglong2 a23 = *(const ulonglong2*)(ad + jj * 16 + 4);
                ulonglong2 a45 = *(const ulonglong2*)(ad + jj * 16 + 8);
                ulonglong2 a67 = *(const ulonglong2*)(ad + jj * 16 + 12);
                u64 t;
                t = relu2(add2(xi[0], xj)); aacc[0] = fma2(t, a01.x, aacc[0]);
                t = relu2(add2(xi[1], xj)); aacc[1] = fma2(t, a01.y, aacc[1]);
                t = relu2(add2(xi[2], xj)); aacc[2] = fma2(t, a23.x, aacc[2]);
                t = relu2(add2(xi[3], xj)); aacc[3] = fma2(t, a23.y, aacc[3]);
                t = relu2(add2(xi[4], xj)); aacc[4] = fma2(t, a45.x, aacc[4]);
                t = relu2(add2(xi[5], xj)); aacc[5] = fma2(t, a45.y, aacc[5]);
                t = relu2(add2(xi[6], xj)); aacc[6] = fma2(t, a67.x, aacc[6]);
                t = relu2(add2(xi[7], xj)); aacc[7] = fma2(t, a67.y, aacc[7]);
            }
            float* o = sPart + jq8 * 1024 + d0;
#pragma unroll
            for (int i = 0; i < 8; i++) *(u64*)(o + i * 128) = aacc[i];
        }
        __syncthreads();
        {   // reduce agg -> dup'd sATs (u64 pairs, single pass)
            u64 v = reduce8_2(sPart, pf0);
            float v0, v1; upk(v, v0, v1);
            *(float2*)(sATs + pc * 20 + 2 * pr) = make_float2(v0, v0);
            *(float2*)(sATs + (pc + 1) * 20 + 2 * pr) = make_float2(v1, v1);
        }
        __syncthreads();

        // ---- nh = relu(Pn + agg@Wc + rs*cb) ----
        {
            u64 acc[4][2] = {};
            gemm_g(sATs, g_Wc[l], lane, rg, kq, acc);
            store_part8(sPart, acc, lane, rg, kq);
            __syncthreads();
            u64 pn = *(const u64*)(sPn + pf0);
            u64 cbp = *(const u64*)(g_cb[l] + pc);
            float rs = s_rs[pr];
            u64 v = relu2(fma2(pk(rs, rs), cbp, add2(reduce8_2(sPart, pf0), pn)));
            float v0, v1; upk(v, v0, v1);
            *(float2*)(sNTs + pc * 20 + 2 * pr) = make_float2(v0, v0);
            *(float2*)(sNTs + (pc + 1) * 20 + 2 * pr) = make_float2(v1, v1);
            __syncthreads();
        }

        // ---- x += nh @ nw2 + nb2 (fused: also writes next layer's dup'd sATs) ----
        {
            u64 acc[4][2] = {};
            gemm_g(sNTs, nw2 + l * 16384, lane, rg, kq, acc);
            store_part8(sPart, acc, lane, rg, kq);
            __syncthreads();
            u64 bb = *(const u64*)(nb2 + l * 128 + pc);
            u64 v = add2(*(const u64*)(sX + pf0), add2(reduce8_2(sPart, pf0), bb));
            *(u64*)(sX + pf0) = v;
            float v0, v1; upk(v, v0, v1);
            *(float2*)(sATs + pc * 20 + 2 * pr) = make_float2(v0, v0);
            *(float2*)(sATs + (pc + 1) * 20 + 2 * pr) = make_float2(v1, v1);
            if (l == L_ - 1) *(u64*)(x + rb * 1024 + pf0) = v;
            __syncthreads();   // sATs/sX/sPart stable before next layer
        }
    }
}

// ---------------- launch ----------------
extern "C" void kernel_launch(void* const* d_in, const int* in_sizes, int n_in,
                              void* d_out, int out_size) {
    const float* nf  = (const float*)d_in[0];
    const float* adj = (const float*)d_in[1];
    const float* ew1 = (const float*)d_in[2];
    const float* eb1 = (const float*)d_in[3];
    const float* ew2 = (const float*)d_in[4];
    const float* eb2 = (const float*)d_in[5];
    const float* nw1 = (const float*)d_in[6];
    const float* nb1 = (const float*)d_in[7];
    const float* nw2 = (const float*)d_in[8];
    const float* nb2 = (const float*)d_in[9];
    float* x = (float*)d_out;

    const int SMEM = SMEM_FLOATS * 4;   // 81956 B
    cudaFuncSetAttribute(k_main, cudaFuncAttributeMaxDynamicSharedMemorySize, SMEM);
    k_main<<<NB, NT, SMEM>>>(x, nf, adj, ew1, eb1, ew2, eb2, nw1, nb1, nw2, nb2);
}